// round 8
// baseline (speedup 1.0000x reference)
#include <cuda_runtime.h>
#include <cuda_bf16.h>
#include <cstdint>

#define NN   50000
#define NPAD 50048              // 391 * 128
#define HID  128
#define NREL 8
#define KC   64
#define NCH  2                  // 128/64
#define NMB  391                // M blocks
#define NB   (NMB * NREL)       // 3128 buckets
#define EMAX 600000
#define ECAP 1024               // smem edge buffer capacity per bucket

// ---------------- scratch (static device globals; no allocation) ----------------
__device__ float g_t[(size_t)NPAD * HID];
__device__ float g_inv[(size_t)NN * NREL];
__device__ __nv_bfloat16 g_bhi1[(NREL * HID + HID) * HID];
__device__ __nv_bfloat16 g_blo1[(NREL * HID + HID) * HID];
__device__ __nv_bfloat16 g_bhi2[(NREL * HID + HID) * HID];
__device__ __nv_bfloat16 g_blo2[(NREL * HID + HID) * HID];
__device__ int g_hist[NB];
__device__ int g_cur[NB];
__device__ int g_boff[NB + 1];
__device__ int2 g_edge[EMAX];   // (src, dst*8+rel), bucket-sorted

// ---------------- helpers ----------------
__device__ __forceinline__ void ldmx4(uint32_t* r, uint32_t addr) {
    asm volatile("ldmatrix.sync.aligned.m8n8.x4.shared.b16 {%0,%1,%2,%3}, [%4];"
                 : "=r"(r[0]), "=r"(r[1]), "=r"(r[2]), "=r"(r[3]) : "r"(addr));
}
__device__ __forceinline__ void mma16816(float* c, const uint32_t* a, const uint32_t* b) {
    asm volatile("mma.sync.aligned.m16n8k16.row.col.f32.bf16.bf16.f32 "
                 "{%0,%1,%2,%3}, {%4,%5,%6,%7}, {%8,%9}, {%0,%1,%2,%3};"
                 : "+f"(c[0]), "+f"(c[1]), "+f"(c[2]), "+f"(c[3])
                 : "r"(a[0]), "r"(a[1]), "r"(a[2]), "r"(a[3]), "r"(b[0]), "r"(b[1]));
}
__device__ __forceinline__ uint32_t smem_u32(const void* p) {
    uint32_t a;
    asm("{ .reg .u64 t; cvta.to.shared.u64 t, %1; cvt.u32.u64 %0, t; }" : "=r"(a) : "l"(p));
    return a;
}
__device__ __forceinline__ void cp_async8(uint32_t saddr, const void* gaddr) {
    asm volatile("cp.async.ca.shared.global [%0], [%1], 8;" :: "r"(saddr), "l"(gaddr));
}
__device__ __forceinline__ void red_add_f32(float* p, float v) {
    asm volatile("red.global.add.f32 [%0], %1;" :: "l"(p), "f"(v) : "memory");
}
__device__ __forceinline__ void red_add_s32(int* p, int v) {
    asm volatile("red.global.add.s32 [%0], %1;" :: "l"(p), "r"(v) : "memory");
}

// ---------------- small kernels ----------------
// 4 edges per thread, fire-and-forget reductions (no return latency)
__global__ void counthist_kernel(const int* __restrict__ src, const int* __restrict__ dst,
                                 const int* __restrict__ rel, int E,
                                 float* __restrict__ cnt, int* __restrict__ hist) {
    int base = (blockIdx.x * blockDim.x + threadIdx.x) * 4;
#pragma unroll
    for (int i = 0; i < 4; i++) {
        int e = base + i;
        if (e < E) {
            int r = __ldg(rel + e);
            red_add_f32(&cnt[__ldg(dst + e) * NREL + r], 1.0f);
            red_add_s32(&hist[(__ldg(src + e) >> 7) * NREL + r], 1);
        }
    }
}
__global__ void inv_kernel(float* __restrict__ cnt, int n) {
    int i = blockIdx.x * blockDim.x + threadIdx.x;
    if (i < n) cnt[i] = 1.0f / fmaxf(cnt[i], 1.0f);
}
__global__ void scan_kernel(const int* __restrict__ hist, int* __restrict__ boff) {
    __shared__ int part[1024];
    int t = threadIdx.x;
    int vals[4];
    int s = 0;
#pragma unroll
    for (int i = 0; i < 4; i++) {
        int b = t * 4 + i;
        vals[i] = (b < NB) ? hist[b] : 0;
        s += vals[i];
    }
    part[t] = s;
    __syncthreads();
    for (int off = 1; off < 1024; off <<= 1) {
        int v = (t >= off) ? part[t - off] : 0;
        __syncthreads();
        part[t] += v;
        __syncthreads();
    }
    int run = (t > 0) ? part[t - 1] : 0;
#pragma unroll
    for (int i = 0; i < 4; i++) {
        int b = t * 4 + i;
        if (b <= NB) boff[b] = run;
        run += vals[i];
    }
    if (t == 1023) boff[NB] = run;
}
// 4 independent edges per thread -> 4 overlapping atomic round-trips
__global__ void reorder_kernel(const int* __restrict__ src, const int* __restrict__ dst,
                               const int* __restrict__ rel, int E,
                               const int* __restrict__ boff, int* __restrict__ cur,
                               int2* __restrict__ edge) {
    int base = (blockIdx.x * blockDim.x + threadIdx.x) * 4;
    int s[4], d[4], r[4], pos[4];
    int n = min(4, E - base);
    if (n <= 0) return;
#pragma unroll
    for (int i = 0; i < 4; i++) {
        if (i < n) {
            s[i] = __ldg(src + base + i);
            d[i] = __ldg(dst + base + i);
            r[i] = __ldg(rel + base + i);
        }
    }
#pragma unroll
    for (int i = 0; i < 4; i++) {
        if (i < n) {
            int b = (s[i] >> 7) * NREL + r[i];
            pos[i] = __ldg(boff + b) + atomicAdd(&cur[b], 1);
        }
    }
#pragma unroll
    for (int i = 0; i < 4; i++)
        if (i < n) edge[pos[i]] = make_int2(s[i], d[i] * NREL + r[i]);
}
__global__ void bconv_kernel(const float* __restrict__ W, const float* __restrict__ root,
                             __nv_bfloat16* __restrict__ bhi, __nv_bfloat16* __restrict__ blo) {
    int i = blockIdx.x * blockDim.x + threadIdx.x;
    if (i >= (NREL * HID + HID) * HID) return;
    int nn = i >> 7, k = i & 127;
    float v = (nn < NREL * HID) ? W[((size_t)(nn >> 7) * HID + k) * HID + (nn & 127)]
                                : root[(size_t)k * HID + (nn - NREL * HID)];
    __nv_bfloat16 h = __float2bfloat16(v);
    bhi[i] = h;
    blo[i] = __float2bfloat16(v - __bfloat162float(h));
}
__global__ void binit_kernel(float* __restrict__ acc, const float* __restrict__ bias, int rows) {
    int i = blockIdx.x * blockDim.x + threadIdx.x;
    if (i >= rows * 32) return;
    ((float4*)acc)[i] = ((const float4*)bias)[i & 31];
}

// ---------------- fused GEMM (+inline fp32->bf16x2 split) + scatter ----------------
// grid (9, 391); smem 72KB: tiles 64KB (reused as fp32 stile), edge buffer 8KB
__global__ void __launch_bounds__(256, 2)
gemm_fused(const float* __restrict__ X, int xrows, int do_relu,
           const __nv_bfloat16* __restrict__ Bhi, const __nv_bfloat16* __restrict__ Blo,
           float* __restrict__ acc_out, int acc_rows,
           const float* __restrict__ inv,
           const int2* __restrict__ edge, const int* __restrict__ boff) {
    extern __shared__ char smem[];
    const uint32_t sbase = smem_u32(smem);
    const uint32_t A_HI = 0, A_LO = 16384, B_HI = 32768, B_LO = 49152, EDG = 65536;
    float* stile = (float*)smem;
    const int2* sedge = (const int2*)(smem + EDG);

    const int tid = threadIdx.x, wid = tid >> 5, lid = tid & 31;
    const int nt = blockIdx.x;                 // 0..7 relations, 8 root
    const int block_row = blockIdx.y * 128;
    const int bcol = nt * 128;
    const int wm = wid >> 2, wn = wid & 3;

    // kick off edge prefetch (relation tiles only)
    int e0 = 0, ecnt = 0;
    if (nt < 8) {
        const int b = blockIdx.y * NREL + nt;
        e0 = boff[b];
        ecnt = boff[b + 1] - e0;
        int pn = min(ecnt, ECAP);
        for (int i = tid; i < pn; i += 256)
            cp_async8(sbase + EDG + i * 8, edge + e0 + i);
    }
    asm volatile("cp.async.commit_group;" ::: "memory");

    const int arow = (lid & 15);
    const uint32_t akoff = (uint32_t)(lid >> 4) * 16;
    const uint32_t axor = (uint32_t)(arow & 7) * 16;
    const int brow = (lid & 7) + ((lid >> 4) * 8);
    const uint32_t bkoff = (uint32_t)((lid >> 3) & 1) * 16;
    const uint32_t bxor = (uint32_t)(brow & 7) * 16;

    float acc[4][4][4];
#pragma unroll
    for (int i = 0; i < 4; i++)
#pragma unroll
        for (int j = 0; j < 4; j++)
#pragma unroll
            for (int v = 0; v < 4; v++) acc[i][j][v] = 0.0f;

    for (int c = 0; c < NCH; c++) {
        // ---- A: fp32 load + relu + hi/lo split, swizzled store ----
#pragma unroll
        for (int i = 0; i < 8; i++) {
            int idx = tid + i * 256;            // 0..2047
            int row = idx >> 4;
            int k4 = (idx & 15) * 4;
            int grow = block_row + row;
            float4 v = make_float4(0.f, 0.f, 0.f, 0.f);
            if (grow < xrows) v = *(const float4*)(X + (size_t)grow * HID + c * KC + k4);
            if (do_relu) {
                v.x = fmaxf(v.x, 0.f); v.y = fmaxf(v.y, 0.f);
                v.z = fmaxf(v.z, 0.f); v.w = fmaxf(v.w, 0.f);
            }
            __nv_bfloat162 h01 = __floats2bfloat162_rn(v.x, v.y);
            __nv_bfloat162 h23 = __floats2bfloat162_rn(v.z, v.w);
            __nv_bfloat162 l01 = __floats2bfloat162_rn(v.x - __bfloat162float(h01.x),
                                                       v.y - __bfloat162float(h01.y));
            __nv_bfloat162 l23 = __floats2bfloat162_rn(v.z - __bfloat162float(h23.x),
                                                       v.w - __bfloat162float(h23.y));
            uint32_t sw = (uint32_t)row * 128 + (((uint32_t)k4 * 2) ^ ((uint32_t)(row & 7) * 16));
            uint2 hv, lv;
            hv.x = *(const uint32_t*)&h01; hv.y = *(const uint32_t*)&h23;
            lv.x = *(const uint32_t*)&l01; lv.y = *(const uint32_t*)&l23;
            *(uint2*)(smem + A_HI + sw) = hv;
            *(uint2*)(smem + A_LO + sw) = lv;
        }
        // ---- B hi/lo ----
#pragma unroll
        for (int i = 0; i < 8; i++) {
            int idx = tid + i * 256;
            int buf = idx >> 10;
            int r = (idx >> 3) & 127;
            int k16 = idx & 7;
            const __nv_bfloat16* srcb = buf ? Blo : Bhi;
            uint4 v = *(const uint4*)(srcb + (size_t)(bcol + r) * HID + c * KC + k16 * 8);
            uint32_t sw = (uint32_t)r * 128 + (((uint32_t)k16 * 16) ^ ((uint32_t)(r & 7) * 16));
            *(uint4*)(smem + (buf ? B_LO : B_HI) + sw) = v;
        }
        __syncthreads();

#pragma unroll
        for (int kk = 0; kk < 4; kk++) {
            uint32_t af[4][4], bf[4][2];
            uint32_t ak = (uint32_t)kk * 32 + akoff;
            uint32_t bk = (uint32_t)kk * 32 + bkoff;

#pragma unroll
            for (int mt = 0; mt < 4; mt++) {
                uint32_t off = (uint32_t)(wm * 64 + mt * 16 + arow) * 128 + (ak ^ axor);
                ldmx4(af[mt], sbase + A_HI + off);
            }
#pragma unroll
            for (int p = 0; p < 2; p++) {
                uint32_t r4[4];
                uint32_t off = (uint32_t)(wn * 32 + p * 16 + brow) * 128 + (bk ^ bxor);
                ldmx4(r4, sbase + B_LO + off);
                bf[2 * p][0] = r4[0]; bf[2 * p][1] = r4[1];
                bf[2 * p + 1][0] = r4[2]; bf[2 * p + 1][1] = r4[3];
            }
#pragma unroll
            for (int mt = 0; mt < 4; mt++)
#pragma unroll
                for (int j = 0; j < 4; j++) mma16816(acc[mt][j], af[mt], bf[j]);

#pragma unroll
            for (int p = 0; p < 2; p++) {
                uint32_t r4[4];
                uint32_t off = (uint32_t)(wn * 32 + p * 16 + brow) * 128 + (bk ^ bxor);
                ldmx4(r4, sbase + B_HI + off);
                bf[2 * p][0] = r4[0]; bf[2 * p][1] = r4[1];
                bf[2 * p + 1][0] = r4[2]; bf[2 * p + 1][1] = r4[3];
            }
#pragma unroll
            for (int mt = 0; mt < 4; mt++)
#pragma unroll
                for (int j = 0; j < 4; j++) mma16816(acc[mt][j], af[mt], bf[j]);

#pragma unroll
            for (int mt = 0; mt < 4; mt++) {
                uint32_t off = (uint32_t)(wm * 64 + mt * 16 + arow) * 128 + (ak ^ axor);
                ldmx4(af[mt], sbase + A_LO + off);
            }
#pragma unroll
            for (int mt = 0; mt < 4; mt++)
#pragma unroll
                for (int j = 0; j < 4; j++) mma16816(acc[mt][j], af[mt], bf[j]);
        }
        __syncthreads();
    }

    if (nt == 8) {
        // root tile: red.add into pre-biased accumulator
#pragma unroll
        for (int mt = 0; mt < 4; mt++) {
            int r0 = block_row + wm * 64 + mt * 16 + (lid >> 2);
#pragma unroll
            for (int j = 0; j < 4; j++) {
                int col = wn * 32 + j * 8 + (lid & 3) * 2;
                if (r0 < acc_rows) {
                    float* p = acc_out + (size_t)r0 * HID + col;
                    asm volatile("red.global.add.v2.f32 [%0], {%1, %2};"
                                 :: "l"(p), "f"(acc[mt][j][0]), "f"(acc[mt][j][1]) : "memory");
                }
                if (r0 + 8 < acc_rows) {
                    float* p = acc_out + (size_t)(r0 + 8) * HID + col;
                    asm volatile("red.global.add.v2.f32 [%0], {%1, %2};"
                                 :: "l"(p), "f"(acc[mt][j][2]), "f"(acc[mt][j][3]) : "memory");
                }
            }
        }
        return;
    }

    // relation tile: stage fp32 tile to smem, scatter bucket edges
#pragma unroll
    for (int mt = 0; mt < 4; mt++) {
        int r0 = wm * 64 + mt * 16 + (lid >> 2);
#pragma unroll
        for (int j = 0; j < 4; j++) {
            int col = wn * 32 + j * 8 + (lid & 3) * 2;
            *(float2*)(stile + r0 * 128 + col)       = make_float2(acc[mt][j][0], acc[mt][j][1]);
            *(float2*)(stile + (r0 + 8) * 128 + col) = make_float2(acc[mt][j][2], acc[mt][j][3]);
        }
    }
    asm volatile("cp.async.wait_group 0;" ::: "memory");
    __syncthreads();

    const int pn = min(ecnt, ECAP);
    for (int e = wid; e < pn; e += 8) {
        int2 ed = sedge[e];
        float sc = inv[ed.y];
        const float4 v = *(const float4*)(stile + (ed.x - block_row) * 128 + lid * 4);
        float4* p = (float4*)(acc_out + (size_t)(ed.y >> 3) * HID) + lid;
        asm volatile("red.global.add.v4.f32 [%0], {%1, %2, %3, %4};"
                     :: "l"(p), "f"(v.x * sc), "f"(v.y * sc), "f"(v.z * sc), "f"(v.w * sc)
                     : "memory");
    }
    // overflow fallback (ecnt > ECAP): read remaining edges from global
    for (int e = ECAP + wid; e < ecnt; e += 8) {
        int2 ed = edge[e0 + e];
        float sc = inv[ed.y];
        const float4 v = *(const float4*)(stile + (ed.x - block_row) * 128 + lid * 4);
        float4* p = (float4*)(acc_out + (size_t)(ed.y >> 3) * HID) + lid;
        asm volatile("red.global.add.v4.f32 [%0], {%1, %2, %3, %4};"
                     :: "l"(p), "f"(v.x * sc), "f"(v.y * sc), "f"(v.z * sc), "f"(v.w * sc)
                     : "memory");
    }
}

// ---------------- launch ----------------
extern "C" void kernel_launch(void* const* d_in, const int* in_sizes, int n_in,
                              void* d_out, int out_size) {
    const int* edge_index = (const int*)d_in[0];
    const int* edge_type  = (const int*)d_in[1];
    const float* node_emb = (const float*)d_in[2];
    const float* W1    = (const float*)d_in[3];
    const float* root1 = (const float*)d_in[4];
    const float* b1    = (const float*)d_in[5];
    const float* W2    = (const float*)d_in[6];
    const float* root2 = (const float*)d_in[7];
    const float* b2    = (const float*)d_in[8];
    float* out = (float*)d_out;

    const int E = in_sizes[0] / 2;
    const int* src = edge_index;
    const int* dst = edge_index + E;

    float *t, *inv;
    __nv_bfloat16 *bhi1, *blo1, *bhi2, *blo2;
    int *hist, *cur, *boff;
    int2* edge;
    cudaGetSymbolAddress((void**)&t,    g_t);
    cudaGetSymbolAddress((void**)&inv,  g_inv);
    cudaGetSymbolAddress((void**)&bhi1, g_bhi1);
    cudaGetSymbolAddress((void**)&blo1, g_blo1);
    cudaGetSymbolAddress((void**)&bhi2, g_bhi2);
    cudaGetSymbolAddress((void**)&blo2, g_blo2);
    cudaGetSymbolAddress((void**)&hist, g_hist);
    cudaGetSymbolAddress((void**)&cur,  g_cur);
    cudaGetSymbolAddress((void**)&boff, g_boff);
    cudaGetSymbolAddress((void**)&edge, g_edge);

    const int T = 256;
    const dim3 gemm_grid(9, NMB);
    const int SMEM_BYTES = 65536 + ECAP * 8;   // 73728
    cudaFuncSetAttribute(gemm_fused, cudaFuncAttributeMaxDynamicSharedMemorySize, SMEM_BYTES);

    // ---- prep (edge structures + both layers' weights + accumulator init) ----
    cudaMemsetAsync(inv, 0, sizeof(float) * (size_t)NN * NREL, 0);
    cudaMemsetAsync(hist, 0, sizeof(int) * NB, 0);
    cudaMemsetAsync(cur, 0, sizeof(int) * NB, 0);
    counthist_kernel<<<(E + T * 4 - 1) / (T * 4), T>>>(src, dst, edge_type, E, inv, hist);
    inv_kernel<<<(NN * NREL + T - 1) / T, T>>>(inv, NN * NREL);
    scan_kernel<<<1, 1024>>>(hist, boff);
    reorder_kernel<<<(E + T * 4 - 1) / (T * 4), T>>>(src, dst, edge_type, E, boff, cur, edge);
    bconv_kernel<<<((NREL * HID + HID) * HID + T - 1) / T, T>>>(W1, root1, bhi1, blo1);
    bconv_kernel<<<((NREL * HID + HID) * HID + T - 1) / T, T>>>(W2, root2, bhi2, blo2);
    binit_kernel<<<(NPAD * 32 + T - 1) / T, T>>>(t, b1, NPAD);
    binit_kernel<<<(NN * 32 + T - 1) / T, T>>>(out, b2, NN);

    // ---- layer 1: A = node_emb (no relu), accumulate into t ----
    gemm_fused<<<gemm_grid, T, SMEM_BYTES>>>(node_emb, NN, 0, bhi1, blo1,
                                             t, NPAD, inv, edge, boff);
    // ---- layer 2: A = relu(t), accumulate into out ----
    gemm_fused<<<gemm_grid, T, SMEM_BYTES>>>(t, NPAD, 1, bhi2, blo2,
                                             out, NN, inv, edge, boff);
}

// round 9
// speedup vs baseline: 1.0163x; 1.0163x over previous
#include <cuda_runtime.h>
#include <cuda_bf16.h>
#include <cstdint>

#define NN   50000
#define NPAD 50048              // 391 * 128
#define HID  128
#define NREL 8
#define KC   64
#define NCH  2                  // 128/64
#define NMB  391                // M blocks
#define NSUB 8                  // sub-buckets per (block, rel): (src>>4)&7
#define NB2  (NMB * NREL * NSUB)    // 25024 buckets
#define EMAX 600000
#define ECAP 1024               // smem edge buffer capacity per (block, rel)

// ---------------- scratch (static device globals; no allocation) ----------------
__device__ float g_t[(size_t)NPAD * HID];
__device__ float g_inv[(size_t)NN * NREL];
__device__ __nv_bfloat16 g_bhi1[(NREL * HID + HID) * HID];
__device__ __nv_bfloat16 g_blo1[(NREL * HID + HID) * HID];
__device__ __nv_bfloat16 g_bhi2[(NREL * HID + HID) * HID];
__device__ __nv_bfloat16 g_blo2[(NREL * HID + HID) * HID];
__device__ int g_hist[NB2];
__device__ int g_cur[NB2];
__device__ int g_boff[NB2 + 1];
__device__ int2 g_edge[EMAX];    // (src, dst), bucket-sorted
__device__ float g_escale[EMAX]; // inv[dst*8+rel], same order

// ---------------- helpers ----------------
__device__ __forceinline__ void ldmx4(uint32_t* r, uint32_t addr) {
    asm volatile("ldmatrix.sync.aligned.m8n8.x4.shared.b16 {%0,%1,%2,%3}, [%4];"
                 : "=r"(r[0]), "=r"(r[1]), "=r"(r[2]), "=r"(r[3]) : "r"(addr));
}
__device__ __forceinline__ void mma16816(float* c, const uint32_t* a, const uint32_t* b) {
    asm volatile("mma.sync.aligned.m16n8k16.row.col.f32.bf16.bf16.f32 "
                 "{%0,%1,%2,%3}, {%4,%5,%6,%7}, {%8,%9}, {%0,%1,%2,%3};"
                 : "+f"(c[0]), "+f"(c[1]), "+f"(c[2]), "+f"(c[3])
                 : "r"(a[0]), "r"(a[1]), "r"(a[2]), "r"(a[3]), "r"(b[0]), "r"(b[1]));
}
__device__ __forceinline__ uint32_t smem_u32(const void* p) {
    uint32_t a;
    asm("{ .reg .u64 t; cvta.to.shared.u64 t, %1; cvt.u32.u64 %0, t; }" : "=r"(a) : "l"(p));
    return a;
}
__device__ __forceinline__ void cp_async8(uint32_t saddr, const void* gaddr) {
    asm volatile("cp.async.ca.shared.global [%0], [%1], 8;" :: "r"(saddr), "l"(gaddr));
}
__device__ __forceinline__ void cp_async4(uint32_t saddr, const void* gaddr) {
    asm volatile("cp.async.ca.shared.global [%0], [%1], 4;" :: "r"(saddr), "l"(gaddr));
}
__device__ __forceinline__ void red_add_f32(float* p, float v) {
    asm volatile("red.global.add.f32 [%0], %1;" :: "l"(p), "f"(v) : "memory");
}
__device__ __forceinline__ void red_add_s32(int* p, int v) {
    asm volatile("red.global.add.s32 [%0], %1;" :: "l"(p), "r"(v) : "memory");
}

// ---------------- small kernels ----------------
__global__ void counthist_kernel(const int* __restrict__ src, const int* __restrict__ dst,
                                 const int* __restrict__ rel, int E,
                                 float* __restrict__ cnt, int* __restrict__ hist) {
    int base = (blockIdx.x * blockDim.x + threadIdx.x) * 4;
#pragma unroll
    for (int i = 0; i < 4; i++) {
        int e = base + i;
        if (e < E) {
            int s = __ldg(src + e);
            int r = __ldg(rel + e);
            red_add_f32(&cnt[__ldg(dst + e) * NREL + r], 1.0f);
            red_add_s32(&hist[((s >> 7) * NREL + r) * NSUB + ((s >> 4) & 7)], 1);
        }
    }
}
__global__ void inv_kernel(float* __restrict__ cnt, int n) {
    int i = blockIdx.x * blockDim.x + threadIdx.x;
    if (i < n) cnt[i] = 1.0f / fmaxf(cnt[i], 1.0f);
}
#define VPT 25   // 1024 * 25 = 25600 >= NB2
__global__ void scan_kernel(const int* __restrict__ hist, int* __restrict__ boff) {
    __shared__ int part[1024];
    int t = threadIdx.x;
    int vals[VPT];
    int s = 0;
#pragma unroll
    for (int i = 0; i < VPT; i++) {
        int b = t * VPT + i;
        vals[i] = (b < NB2) ? hist[b] : 0;
        s += vals[i];
    }
    part[t] = s;
    __syncthreads();
    for (int off = 1; off < 1024; off <<= 1) {
        int v = (t >= off) ? part[t - off] : 0;
        __syncthreads();
        part[t] += v;
        __syncthreads();
    }
    int run = (t > 0) ? part[t - 1] : 0;
#pragma unroll
    for (int i = 0; i < VPT; i++) {
        int b = t * VPT + i;
        if (b <= NB2) boff[b] = run;
        run += vals[i];
    }
    if (t == 1023) boff[NB2] = run;
}
// 4 independent edges/thread; finer buckets cut per-address contention 8x.
// Stores edge=(src,dst) and scale=inv[dst*8+rel] so the GEMM epilogue is load-free.
__global__ void reorder_kernel(const int* __restrict__ src, const int* __restrict__ dst,
                               const int* __restrict__ rel, int E,
                               const int* __restrict__ boff, int* __restrict__ cur,
                               const float* __restrict__ inv,
                               int2* __restrict__ edge, float* __restrict__ escale) {
    int base = (blockIdx.x * blockDim.x + threadIdx.x) * 4;
    int s[4], d[4], r[4], pos[4];
    float sc[4];
    int n = min(4, E - base);
    if (n <= 0) return;
#pragma unroll
    for (int i = 0; i < 4; i++) {
        if (i < n) {
            s[i] = __ldg(src + base + i);
            d[i] = __ldg(dst + base + i);
            r[i] = __ldg(rel + base + i);
        }
    }
#pragma unroll
    for (int i = 0; i < 4; i++) {
        if (i < n) {
            int b = ((s[i] >> 7) * NREL + r[i]) * NSUB + ((s[i] >> 4) & 7);
            pos[i] = __ldg(boff + b) + atomicAdd(&cur[b], 1);
            sc[i] = __ldg(inv + d[i] * NREL + r[i]);
        }
    }
#pragma unroll
    for (int i = 0; i < 4; i++) {
        if (i < n) {
            edge[pos[i]] = make_int2(s[i], d[i]);
            escale[pos[i]] = sc[i];
        }
    }
}
__global__ void bconv_kernel(const float* __restrict__ W, const float* __restrict__ root,
                             __nv_bfloat16* __restrict__ bhi, __nv_bfloat16* __restrict__ blo) {
    int i = blockIdx.x * blockDim.x + threadIdx.x;
    if (i >= (NREL * HID + HID) * HID) return;
    int nn = i >> 7, k = i & 127;
    float v = (nn < NREL * HID) ? W[((size_t)(nn >> 7) * HID + k) * HID + (nn & 127)]
                                : root[(size_t)k * HID + (nn - NREL * HID)];
    __nv_bfloat16 h = __float2bfloat16(v);
    bhi[i] = h;
    blo[i] = __float2bfloat16(v - __bfloat162float(h));
}
__global__ void binit_kernel(float* __restrict__ acc, const float* __restrict__ bias, int rows) {
    int i = blockIdx.x * blockDim.x + threadIdx.x;
    if (i >= rows * 32) return;
    ((float4*)acc)[i] = ((const float4*)bias)[i & 31];
}

// ---------------- fused GEMM (+inline fp32->bf16x2 split) + scatter ----------------
// grid (9, 391); smem 76KB: tiles 64KB (reused as fp32 stile), edges 8KB, scales 4KB
__global__ void __launch_bounds__(256, 2)
gemm_fused(const float* __restrict__ X, int xrows, int do_relu,
           const __nv_bfloat16* __restrict__ Bhi, const __nv_bfloat16* __restrict__ Blo,
           float* __restrict__ acc_out, int acc_rows,
           const int2* __restrict__ edge, const float* __restrict__ escale,
           const int* __restrict__ boff) {
    extern __shared__ char smem[];
    const uint32_t sbase = smem_u32(smem);
    const uint32_t A_HI = 0, A_LO = 16384, B_HI = 32768, B_LO = 49152;
    const uint32_t EDG = 65536, ESC = 65536 + ECAP * 8;
    float* stile = (float*)smem;
    const int2* sedge = (const int2*)(smem + EDG);
    const float* sscale = (const float*)(smem + ESC);

    const int tid = threadIdx.x, wid = tid >> 5, lid = tid & 31;
    const int nt = blockIdx.x;                 // 0..7 relations, 8 root
    const int block_row = blockIdx.y * 128;
    const int bcol = nt * 128;
    const int wm = wid >> 2, wn = wid & 3;

    // kick off edge + scale prefetch (relation tiles only)
    int e0 = 0, ecnt = 0;
    if (nt < 8) {
        const int b8 = (blockIdx.y * NREL + nt) * NSUB;
        e0 = boff[b8];
        ecnt = boff[b8 + NSUB] - e0;
        int pn = min(ecnt, ECAP);
        for (int i = tid; i < pn; i += 256) {
            cp_async8(sbase + EDG + i * 8, edge + e0 + i);
            cp_async4(sbase + ESC + i * 4, escale + e0 + i);
        }
    }
    asm volatile("cp.async.commit_group;" ::: "memory");

    const int arow = (lid & 15);
    const uint32_t akoff = (uint32_t)(lid >> 4) * 16;
    const uint32_t axor = (uint32_t)(arow & 7) * 16;
    const int brow = (lid & 7) + ((lid >> 4) * 8);
    const uint32_t bkoff = (uint32_t)((lid >> 3) & 1) * 16;
    const uint32_t bxor = (uint32_t)(brow & 7) * 16;

    float acc[4][4][4];
#pragma unroll
    for (int i = 0; i < 4; i++)
#pragma unroll
        for (int j = 0; j < 4; j++)
#pragma unroll
            for (int v = 0; v < 4; v++) acc[i][j][v] = 0.0f;

    for (int c = 0; c < NCH; c++) {
        // ---- A: fp32 load + relu + hi/lo split, swizzled store ----
#pragma unroll
        for (int i = 0; i < 8; i++) {
            int idx = tid + i * 256;            // 0..2047
            int row = idx >> 4;
            int k4 = (idx & 15) * 4;
            int grow = block_row + row;
            float4 v = make_float4(0.f, 0.f, 0.f, 0.f);
            if (grow < xrows) v = *(const float4*)(X + (size_t)grow * HID + c * KC + k4);
            if (do_relu) {
                v.x = fmaxf(v.x, 0.f); v.y = fmaxf(v.y, 0.f);
                v.z = fmaxf(v.z, 0.f); v.w = fmaxf(v.w, 0.f);
            }
            __nv_bfloat162 h01 = __floats2bfloat162_rn(v.x, v.y);
            __nv_bfloat162 h23 = __floats2bfloat162_rn(v.z, v.w);
            __nv_bfloat162 l01 = __floats2bfloat162_rn(v.x - __bfloat162float(h01.x),
                                                       v.y - __bfloat162float(h01.y));
            __nv_bfloat162 l23 = __floats2bfloat162_rn(v.z - __bfloat162float(h23.x),
                                                       v.w - __bfloat162float(h23.y));
            uint32_t sw = (uint32_t)row * 128 + (((uint32_t)k4 * 2) ^ ((uint32_t)(row & 7) * 16));
            uint2 hv, lv;
            hv.x = *(const uint32_t*)&h01; hv.y = *(const uint32_t*)&h23;
            lv.x = *(const uint32_t*)&l01; lv.y = *(const uint32_t*)&l23;
            *(uint2*)(smem + A_HI + sw) = hv;
            *(uint2*)(smem + A_LO + sw) = lv;
        }
        // ---- B hi/lo ----
#pragma unroll
        for (int i = 0; i < 8; i++) {
            int idx = tid + i * 256;
            int buf = idx >> 10;
            int r = (idx >> 3) & 127;
            int k16 = idx & 7;
            const __nv_bfloat16* srcb = buf ? Blo : Bhi;
            uint4 v = *(const uint4*)(srcb + (size_t)(bcol + r) * HID + c * KC + k16 * 8);
            uint32_t sw = (uint32_t)r * 128 + (((uint32_t)k16 * 16) ^ ((uint32_t)(r & 7) * 16));
            *(uint4*)(smem + (buf ? B_LO : B_HI) + sw) = v;
        }
        __syncthreads();

#pragma unroll
        for (int kk = 0; kk < 4; kk++) {
            uint32_t af[4][4], bf[4][2];
            uint32_t ak = (uint32_t)kk * 32 + akoff;
            uint32_t bk = (uint32_t)kk * 32 + bkoff;

#pragma unroll
            for (int mt = 0; mt < 4; mt++) {
                uint32_t off = (uint32_t)(wm * 64 + mt * 16 + arow) * 128 + (ak ^ axor);
                ldmx4(af[mt], sbase + A_HI + off);
            }
#pragma unroll
            for (int p = 0; p < 2; p++) {
                uint32_t r4[4];
                uint32_t off = (uint32_t)(wn * 32 + p * 16 + brow) * 128 + (bk ^ bxor);
                ldmx4(r4, sbase + B_LO + off);
                bf[2 * p][0] = r4[0]; bf[2 * p][1] = r4[1];
                bf[2 * p + 1][0] = r4[2]; bf[2 * p + 1][1] = r4[3];
            }
#pragma unroll
            for (int mt = 0; mt < 4; mt++)
#pragma unroll
                for (int j = 0; j < 4; j++) mma16816(acc[mt][j], af[mt], bf[j]);

#pragma unroll
            for (int p = 0; p < 2; p++) {
                uint32_t r4[4];
                uint32_t off = (uint32_t)(wn * 32 + p * 16 + brow) * 128 + (bk ^ bxor);
                ldmx4(r4, sbase + B_HI + off);
                bf[2 * p][0] = r4[0]; bf[2 * p][1] = r4[1];
                bf[2 * p + 1][0] = r4[2]; bf[2 * p + 1][1] = r4[3];
            }
#pragma unroll
            for (int mt = 0; mt < 4; mt++)
#pragma unroll
                for (int j = 0; j < 4; j++) mma16816(acc[mt][j], af[mt], bf[j]);

#pragma unroll
            for (int mt = 0; mt < 4; mt++) {
                uint32_t off = (uint32_t)(wm * 64 + mt * 16 + arow) * 128 + (ak ^ axor);
                ldmx4(af[mt], sbase + A_LO + off);
            }
#pragma unroll
            for (int mt = 0; mt < 4; mt++)
#pragma unroll
                for (int j = 0; j < 4; j++) mma16816(acc[mt][j], af[mt], bf[j]);
        }
        __syncthreads();
    }

    if (nt == 8) {
        // root tile: red.add into pre-biased accumulator
#pragma unroll
        for (int mt = 0; mt < 4; mt++) {
            int r0 = block_row + wm * 64 + mt * 16 + (lid >> 2);
#pragma unroll
            for (int j = 0; j < 4; j++) {
                int col = wn * 32 + j * 8 + (lid & 3) * 2;
                if (r0 < acc_rows) {
                    float* p = acc_out + (size_t)r0 * HID + col;
                    asm volatile("red.global.add.v2.f32 [%0], {%1, %2};"
                                 :: "l"(p), "f"(acc[mt][j][0]), "f"(acc[mt][j][1]) : "memory");
                }
                if (r0 + 8 < acc_rows) {
                    float* p = acc_out + (size_t)(r0 + 8) * HID + col;
                    asm volatile("red.global.add.v2.f32 [%0], {%1, %2};"
                                 :: "l"(p), "f"(acc[mt][j][2]), "f"(acc[mt][j][3]) : "memory");
                }
            }
        }
        return;
    }

    // relation tile: stage fp32 tile to smem, scatter bucket edges
#pragma unroll
    for (int mt = 0; mt < 4; mt++) {
        int r0 = wm * 64 + mt * 16 + (lid >> 2);
#pragma unroll
        for (int j = 0; j < 4; j++) {
            int col = wn * 32 + j * 8 + (lid & 3) * 2;
            *(float2*)(stile + r0 * 128 + col)       = make_float2(acc[mt][j][0], acc[mt][j][1]);
            *(float2*)(stile + (r0 + 8) * 128 + col) = make_float2(acc[mt][j][2], acc[mt][j][3]);
        }
    }
    asm volatile("cp.async.wait_group 0;" ::: "memory");
    __syncthreads();

    const int pn = min(ecnt, ECAP);
    for (int e = wid; e < pn; e += 8) {
        int2 ed = sedge[e];
        float sc = sscale[e];
        const float4 v = *(const float4*)(stile + (ed.x - block_row) * 128 + lid * 4);
        float4* p = (float4*)(acc_out + (size_t)ed.y * HID) + lid;
        asm volatile("red.global.add.v4.f32 [%0], {%1, %2, %3, %4};"
                     :: "l"(p), "f"(v.x * sc), "f"(v.y * sc), "f"(v.z * sc), "f"(v.w * sc)
                     : "memory");
    }
    // overflow fallback (ecnt > ECAP)
    for (int e = ECAP + wid; e < ecnt; e += 8) {
        int2 ed = edge[e0 + e];
        float sc = escale[e0 + e];
        const float4 v = *(const float4*)(stile + (ed.x - block_row) * 128 + lid * 4);
        float4* p = (float4*)(acc_out + (size_t)ed.y * HID) + lid;
        asm volatile("red.global.add.v4.f32 [%0], {%1, %2, %3, %4};"
                     :: "l"(p), "f"(v.x * sc), "f"(v.y * sc), "f"(v.z * sc), "f"(v.w * sc)
                     : "memory");
    }
}

// ---------------- launch ----------------
extern "C" void kernel_launch(void* const* d_in, const int* in_sizes, int n_in,
                              void* d_out, int out_size) {
    const int* edge_index = (const int*)d_in[0];
    const int* edge_type  = (const int*)d_in[1];
    const float* node_emb = (const float*)d_in[2];
    const float* W1    = (const float*)d_in[3];
    const float* root1 = (const float*)d_in[4];
    const float* b1    = (const float*)d_in[5];
    const float* W2    = (const float*)d_in[6];
    const float* root2 = (const float*)d_in[7];
    const float* b2    = (const float*)d_in[8];
    float* out = (float*)d_out;

    const int E = in_sizes[0] / 2;
    const int* src = edge_index;
    const int* dst = edge_index + E;

    float *t, *inv, *escale;
    __nv_bfloat16 *bhi1, *blo1, *bhi2, *blo2;
    int *hist, *cur, *boff;
    int2* edge;
    cudaGetSymbolAddress((void**)&t,      g_t);
    cudaGetSymbolAddress((void**)&inv,    g_inv);
    cudaGetSymbolAddress((void**)&bhi1,   g_bhi1);
    cudaGetSymbolAddress((void**)&blo1,   g_blo1);
    cudaGetSymbolAddress((void**)&bhi2,   g_bhi2);
    cudaGetSymbolAddress((void**)&blo2,   g_blo2);
    cudaGetSymbolAddress((void**)&hist,   g_hist);
    cudaGetSymbolAddress((void**)&cur,    g_cur);
    cudaGetSymbolAddress((void**)&boff,   g_boff);
    cudaGetSymbolAddress((void**)&edge,   g_edge);
    cudaGetSymbolAddress((void**)&escale, g_escale);

    const int T = 256;
    const dim3 gemm_grid(9, NMB);
    const int SMEM_BYTES = 65536 + ECAP * 8 + ECAP * 4;   // 77824
    cudaFuncSetAttribute(gemm_fused, cudaFuncAttributeMaxDynamicSharedMemorySize, SMEM_BYTES);

    // ---- prep ----
    cudaMemsetAsync(inv, 0, sizeof(float) * (size_t)NN * NREL, 0);
    cudaMemsetAsync(hist, 0, sizeof(int) * NB2, 0);
    cudaMemsetAsync(cur, 0, sizeof(int) * NB2, 0);
    counthist_kernel<<<(E + T * 4 - 1) / (T * 4), T>>>(src, dst, edge_type, E, inv, hist);
    inv_kernel<<<(NN * NREL + T - 1) / T, T>>>(inv, NN * NREL);
    scan_kernel<<<1, 1024>>>(hist, boff);
    reorder_kernel<<<(E + T * 4 - 1) / (T * 4), T>>>(src, dst, edge_type, E, boff, cur,
                                                     inv, edge, escale);
    bconv_kernel<<<((NREL * HID + HID) * HID + T - 1) / T, T>>>(W1, root1, bhi1, blo1);
    bconv_kernel<<<((NREL * HID + HID) * HID + T - 1) / T, T>>>(W2, root2, bhi2, blo2);
    binit_kernel<<<(NPAD * 32 + T - 1) / T, T>>>(t, b1, NPAD);
    binit_kernel<<<(NN * 32 + T - 1) / T, T>>>(out, b2, NN);

    // ---- layer 1: A = node_emb (no relu), accumulate into t ----
    gemm_fused<<<gemm_grid, T, SMEM_BYTES>>>(node_emb, NN, 0, bhi1, blo1,
                                             t, NPAD, edge, escale, boff);
    // ---- layer 2: A = relu(t), accumulate into out ----
    gemm_fused<<<gemm_grid, T, SMEM_BYTES>>>(t, NPAD, 1, bhi2, blo2,
                                             out, NN, edge, escale, boff);
}